// round 6
// baseline (speedup 1.0000x reference)
#include <cuda_runtime.h>
#include <cuda_bf16.h>
#include <math.h>

#define H 1024
#define W 1024
#define PAD 8
#define HP (H + 2 * PAD)   // 1040 padded rows
#define BIGF 1e10f
#define SENT (1 << 30)

// Padded intermediate: rows [0,8) and [1032,1040) are BIGF.
// Row r of the image lives at padded row r+PAD.
__device__ float g_f2[HP * W];

__device__ __forceinline__ float sqrt_approx(float x) {
    float r;
    asm("sqrt.approx.f32 %0, %1;" : "=f"(r) : "f"(x));
    return r;
}

// ---------------------------------------------------------------------------
// Pass 1: TWO warps per row (16 px/lane, 16-bit zero masks).
// Block = 512 threads = 16 warps = 8 padded rows. Warp pair (half 0/1)
// exchanges half-row aggregates through smem. Pad rows run the same uniform
// path with mask=0 and sentinel carries -> d >= 2^29 -> BIGF.
// Matches reference int arithmetic exactly.
// ---------------------------------------------------------------------------
__global__ void __launch_bounds__(512) row_dist_kernel(const float* __restrict__ img) {
    __shared__ int sL[8];  // half-0 total (max zero idx) per local row
    __shared__ int sR[8];  // half-1 total (min zero idx) per local row

    const int tid = threadIdx.x;
    const int lane = tid & 31;
    const int w = tid >> 5;
    const int rlocal = w >> 1;
    const int half = w & 1;
    const int prow = blockIdx.x * 8 + rlocal;       // padded row 0..1039
    const bool valid = (prow >= PAD) && (prow < H + PAD);
    const int base = half * 512 + lane * 16;        // first pixel owned

    unsigned mask = 0u;
    if (valid) {
        const float4* __restrict__ i4 =
            (const float4*)(img + (prow - PAD) * W) + base / 4;
        float4 v0 = i4[0], v1 = i4[1], v2 = i4[2], v3 = i4[3];
        const float* pv = (const float*)&v0;  // v0..v3 contiguous? not guaranteed
        // build mask explicitly per vector to stay register-resident
        #define MB(vv, off) \
            if ((vv).x == 0.0f) mask |= 1u << ((off) + 0); \
            if ((vv).y == 0.0f) mask |= 1u << ((off) + 1); \
            if ((vv).z == 0.0f) mask |= 1u << ((off) + 2); \
            if ((vv).w == 0.0f) mask |= 1u << ((off) + 3);
        MB(v0, 0) MB(v1, 4) MB(v2, 8) MB(v3, 12)
        #undef MB
        (void)pv;
    }

    // Lane aggregates over its 16 pixels.
    const int aggL = mask ? (base + 31 - __clz(mask)) : -SENT;
    const int aggR = mask ? (base + __ffs(mask) - 1) : SENT;

    // Warp-level scans (within the 512-px half-row).
    int a = aggL;
    #pragma unroll
    for (int o = 1; o < 32; o <<= 1) {
        int t = __shfl_up_sync(0xffffffffu, a, o);
        if (lane >= o) a = max(a, t);
    }
    int carryL = __shfl_up_sync(0xffffffffu, a, 1);
    if (lane == 0) carryL = -SENT;

    int b = aggR;
    #pragma unroll
    for (int o = 1; o < 32; o <<= 1) {
        int t = __shfl_down_sync(0xffffffffu, b, o);
        if (lane < 32 - o) b = min(b, t);
    }
    int carryR = __shfl_down_sync(0xffffffffu, b, 1);
    if (lane == 31) carryR = SENT;

    // Cross-half exchange: half1 needs half0's total max; half0 needs half1's total min.
    const int totL = __shfl_sync(0xffffffffu, a, 31);
    const int totR = __shfl_sync(0xffffffffu, b, 0);
    if (lane == 0 && half == 0) sL[rlocal] = totL;
    if (lane == 0 && half == 1) sR[rlocal] = totR;
    __syncthreads();
    if (half == 1) carryL = max(carryL, sL[rlocal]);
    else           carryR = min(carryR, sR[rlocal]);

    // Per-pixel distances from the 16-bit mask.
    float res[16];
    #pragma unroll
    for (int p = 0; p < 16; p++) {
        const int idx = base + p;
        const unsigned ml = mask & (0xFFFFu >> (15 - p));
        const unsigned mr = mask & (0xFFFFu << p);
        const int zl = ml ? (base + 31 - __clz(ml)) : carryL;
        const int zr = mr ? (base + __ffs(mr) - 1) : carryR;
        const int d = min(idx - zl, zr - idx);
        const float df = (float)d;
        res[p] = (d >= (1 << 29)) ? BIGF : df * df;
    }

    float4* __restrict__ o4 = (float4*)(g_f2 + prow * W) + base / 4;
    #pragma unroll
    for (int q = 0; q < 4; q++) {
        o4[q] = make_float4(res[q * 4], res[q * 4 + 1], res[q * 4 + 2], res[q * 4 + 3]);
    }
}

// ---------------------------------------------------------------------------
// Pass 2: out[i,j] = sqrt( min_k f2[k,j] + (i-k)^2 ).
// Branchless: padded g_f2 needs no bounds checks. Each thread handles
// 2 consecutive columns x 8 rows via 24 float2 loads (front-batched MLP).
// Exactness: m <= 64 => +-8 window min is global min; else exact full-column
// fallback (prob ~2^-17 per pixel on any input with this check).
// ---------------------------------------------------------------------------
__global__ void __launch_bounds__(256) col_parabola_kernel(float* __restrict__ out) {
    const int fidx = blockIdx.x * 256 + threadIdx.x;  // float2 column index
    const int ib = blockIdx.y * 8;                    // output row base

    const float2* __restrict__ f2p = (const float2*)g_f2;

    // Padded rows ib .. ib+23 cover windows of output rows ib..ib+7.
    float2 win[24];
    #pragma unroll
    for (int k = 0; k < 24; k++) win[k] = f2p[(ib + k) * (W / 2) + fidx];

    float2 m[8];
    #pragma unroll
    for (int u = 0; u < 8; u++) m[u] = win[u + 8];  // d = 0 tap
    #pragma unroll
    for (int d = 1; d <= 8; d++) {
        const float dd = (float)(d * d);
        #pragma unroll
        for (int u = 0; u < 8; u++) {
            m[u].x = fminf(m[u].x, win[u + 8 - d].x + dd);
            m[u].x = fminf(m[u].x, win[u + 8 + d].x + dd);
            m[u].y = fminf(m[u].y, win[u + 8 - d].y + dd);
            m[u].y = fminf(m[u].y, win[u + 8 + d].y + dd);
        }
    }

    float2* __restrict__ out2 = (float2*)out;
    #pragma unroll
    for (int u = 0; u < 8; u++) {
        const int i = ib + u;
        float mx = m[u].x, my = m[u].y;
        if (mx > 64.0f) {  // exact fallback (astronomically rare)
            mx = 3.4e38f;
            for (int k = 0; k < H; k++) {
                const float di = (float)(i - k);
                mx = fminf(mx, g_f2[(k + PAD) * W + fidx * 2] + di * di);
            }
        }
        if (my > 64.0f) {
            my = 3.4e38f;
            for (int k = 0; k < H; k++) {
                const float di = (float)(i - k);
                my = fminf(my, g_f2[(k + PAD) * W + fidx * 2 + 1] + di * di);
            }
        }
        out2[i * (W / 2) + fidx] = make_float2(sqrt_approx(mx), sqrt_approx(my));
    }
}

// ---------------------------------------------------------------------------
extern "C" void kernel_launch(void* const* d_in, const int* in_sizes, int n_in,
                              void* d_out, int out_size) {
    const float* img = (const float*)d_in[0];
    float* out = (float*)d_out;

    row_dist_kernel<<<130, 512>>>(img);   // 130 blocks x 8 padded rows = 1040

    dim3 grid(W / 2 / 256, H / 8);        // (2, 128) = 256 CTAs
    col_parabola_kernel<<<grid, 256>>>(out);
}

// round 8
// speedup vs baseline: 1.0533x; 1.0533x over previous
#include <cuda_runtime.h>
#include <cuda_bf16.h>
#include <math.h>

#define H 1024
#define W 1024
#define PAD 8
#define HP (H + 2 * PAD)   // 1040 padded rows
#define BIGF 1e10f
#define SENT (1 << 30)

// Padded intermediate: padded rows [0,8) and [1032,1040) hold BIGF.
// Image row r lives at padded row r+PAD.
__device__ float g_f2[HP * W];

__device__ __forceinline__ float sqrt_approx(float x) {
    float r;
    asm("sqrt.approx.f32 %0, %1;" : "=f"(r) : "f"(x));
    return r;
}

// ---------------------------------------------------------------------------
// Pass 1: FOUR warps per row (8 px/lane, 8-bit zero masks).
// Block = 512 threads = 16 warps = 4 padded rows. Quarter-row warps exchange
// aggregates via a 4x4 smem table. Pad rows take the same uniform path
// (mask=0, sentinel carries -> BIGF). Matches reference int math exactly.
// ---------------------------------------------------------------------------
__global__ void __launch_bounds__(512) row_dist_kernel(const float* __restrict__ img) {
    __shared__ int sL[4][4];  // [rlocal][quarter] max-zero-idx totals
    __shared__ int sR[4][4];  // [rlocal][quarter] min-zero-idx totals

    const int tid = threadIdx.x;
    const int lane = tid & 31;
    const int w = tid >> 5;
    const int rlocal = w >> 2;        // 0..3
    const int quarter = w & 3;        // 0..3
    const int prow = blockIdx.x * 4 + rlocal;        // padded row 0..1039
    const bool valid = (prow >= PAD) && (prow < H + PAD);
    const int base = quarter * 256 + lane * 8;       // first pixel owned

    unsigned mask = 0u;
    if (valid) {
        const float4* __restrict__ i4 =
            (const float4*)(img + (prow - PAD) * W) + base / 4;
        const float4 v0 = i4[0], v1 = i4[1];
        if (v0.x == 0.0f) mask |= 1u;
        if (v0.y == 0.0f) mask |= 2u;
        if (v0.z == 0.0f) mask |= 4u;
        if (v0.w == 0.0f) mask |= 8u;
        if (v1.x == 0.0f) mask |= 16u;
        if (v1.y == 0.0f) mask |= 32u;
        if (v1.z == 0.0f) mask |= 64u;
        if (v1.w == 0.0f) mask |= 128u;
    }

    // Lane aggregates over its 8 pixels.
    const int aggL = mask ? (base + 31 - __clz(mask)) : -SENT;
    const int aggR = mask ? (base + __ffs(mask) - 1) : SENT;

    // Warp scans (within the 256-px quarter-row).
    int a = aggL;
    #pragma unroll
    for (int o = 1; o < 32; o <<= 1) {
        int t = __shfl_up_sync(0xffffffffu, a, o);
        if (lane >= o) a = max(a, t);
    }
    int carryL = __shfl_up_sync(0xffffffffu, a, 1);
    if (lane == 0) carryL = -SENT;

    int b = aggR;
    #pragma unroll
    for (int o = 1; o < 32; o <<= 1) {
        int t = __shfl_down_sync(0xffffffffu, b, o);
        if (lane < 32 - o) b = min(b, t);
    }
    int carryR = __shfl_down_sync(0xffffffffu, b, 1);
    if (lane == 31) carryR = SENT;

    // Warp totals — shuffles executed by ALL lanes (convergent), stores by lane 0.
    const int totL = __shfl_sync(0xffffffffu, a, 31);  // inclusive max at lane 31
    const int totR = __shfl_sync(0xffffffffu, b, 0);   // inclusive min at lane 0
    if (lane == 0) {
        sL[rlocal][quarter] = totL;
        sR[rlocal][quarter] = totR;
    }
    __syncthreads();
    #pragma unroll
    for (int q = 0; q < 4; q++) {
        if (q < quarter) carryL = max(carryL, sL[rlocal][q]);
        if (q > quarter) carryR = min(carryR, sR[rlocal][q]);
    }

    // Per-pixel distances from the 8-bit mask.
    float res[8];
    #pragma unroll
    for (int p = 0; p < 8; p++) {
        const int idx = base + p;
        const unsigned ml = mask & (0xFFu >> (7 - p));
        const unsigned mr = mask & (0xFFu << p);
        const int zl = ml ? (base + 31 - __clz(ml)) : carryL;
        const int zr = mr ? (base + __ffs(mr) - 1) : carryR;
        const int d = min(idx - zl, zr - idx);
        const float df = (float)d;
        res[p] = (d >= (1 << 29)) ? BIGF : df * df;
    }

    float4* __restrict__ o4 = (float4*)(g_f2 + prow * W) + base / 4;
    o4[0] = make_float4(res[0], res[1], res[2], res[3]);
    o4[1] = make_float4(res[4], res[5], res[6], res[7]);
}

// ---------------------------------------------------------------------------
// Pass 2: out[i,j] = sqrt( min_k f2[k,j] + (i-k)^2 ).
// Branchless (padded g_f2). One column x 4 rows per thread: 20 independent
// coalesced loads -> 4 interleaved 17-tap fmin chains in registers.
// Exactness: m <= 64 => +-8 window min is the global min ((i-k)^2 >= 81
// outside); else exact full-column fallback (prob ~2^-17 per pixel).
// ---------------------------------------------------------------------------
__global__ void __launch_bounds__(256) col_parabola_kernel(float* __restrict__ out) {
    const int j = blockIdx.x * 256 + threadIdx.x;  // column
    const int ib = blockIdx.y * 4;                 // first output row (== padded base)

    // Padded rows ib..ib+19 cover the +-8 windows of output rows ib..ib+3.
    float win[20];
    #pragma unroll
    for (int k = 0; k < 20; k++) win[k] = g_f2[(ib + k) * W + j];

    float m[4];
    #pragma unroll
    for (int u = 0; u < 4; u++) m[u] = win[u + 8];  // d = 0 tap
    #pragma unroll
    for (int d = 1; d <= 8; d++) {
        const float dd = (float)(d * d);
        #pragma unroll
        for (int u = 0; u < 4; u++) {
            m[u] = fminf(m[u], win[u + 8 - d] + dd);
            m[u] = fminf(m[u], win[u + 8 + d] + dd);
        }
    }

    #pragma unroll
    for (int u = 0; u < 4; u++) {
        const int i = ib + u;
        float mv = m[u];
        if (mv > 64.0f) {  // exact fallback (astronomically rare)
            mv = 3.4e38f;
            for (int k = 0; k < H; k++) {
                const float di = (float)(i - k);
                mv = fminf(mv, g_f2[(k + PAD) * W + j] + di * di);
            }
        }
        out[i * W + j] = sqrt_approx(mv);
    }
}

// ---------------------------------------------------------------------------
extern "C" void kernel_launch(void* const* d_in, const int* in_sizes, int n_in,
                              void* d_out, int out_size) {
    const float* img = (const float*)d_in[0];
    float* out = (float*)d_out;

    row_dist_kernel<<<260, 512>>>(img);   // 260 blocks x 4 padded rows = 1040

    dim3 grid(W / 256, H / 4);            // (4, 256) = 1024 CTAs
    col_parabola_kernel<<<grid, 256>>>(out);
}

// round 9
// speedup vs baseline: 1.1160x; 1.0596x over previous
#include <cuda_runtime.h>
#include <cuda_bf16.h>
#include <math.h>

#define H 1024
#define W 1024
#define PAD 8
#define HP (H + 2 * PAD)   // 1040 padded rows
#define BIGF 1e10f
#define SENT (1 << 30)

// Padded intermediate: padded rows [0,8) and [1032,1040) hold BIGF.
// Image row r lives at padded row r+PAD.
__device__ float g_f2[HP * W];

__device__ __forceinline__ float sqrt_approx(float x) {
    float r;
    asm("sqrt.approx.f32 %0, %1;" : "=f"(r) : "f"(x));
    return r;
}

// ---------------------------------------------------------------------------
// Pass 1: FOUR warps per row (8 px/lane, 8-bit zero masks). Same as round 8.
// ---------------------------------------------------------------------------
__global__ void __launch_bounds__(512) row_dist_kernel(const float* __restrict__ img) {
    __shared__ int sL[4][4];
    __shared__ int sR[4][4];

    const int tid = threadIdx.x;
    const int lane = tid & 31;
    const int w = tid >> 5;
    const int rlocal = w >> 2;
    const int quarter = w & 3;
    const int prow = blockIdx.x * 4 + rlocal;
    const bool valid = (prow >= PAD) && (prow < H + PAD);
    const int base = quarter * 256 + lane * 8;

    unsigned mask = 0u;
    if (valid) {
        const float4* __restrict__ i4 =
            (const float4*)(img + (prow - PAD) * W) + base / 4;
        const float4 v0 = i4[0], v1 = i4[1];
        if (v0.x == 0.0f) mask |= 1u;
        if (v0.y == 0.0f) mask |= 2u;
        if (v0.z == 0.0f) mask |= 4u;
        if (v0.w == 0.0f) mask |= 8u;
        if (v1.x == 0.0f) mask |= 16u;
        if (v1.y == 0.0f) mask |= 32u;
        if (v1.z == 0.0f) mask |= 64u;
        if (v1.w == 0.0f) mask |= 128u;
    }

    const int aggL = mask ? (base + 31 - __clz(mask)) : -SENT;
    const int aggR = mask ? (base + __ffs(mask) - 1) : SENT;

    int a = aggL;
    #pragma unroll
    for (int o = 1; o < 32; o <<= 1) {
        int t = __shfl_up_sync(0xffffffffu, a, o);
        if (lane >= o) a = max(a, t);
    }
    int carryL = __shfl_up_sync(0xffffffffu, a, 1);
    if (lane == 0) carryL = -SENT;

    int b = aggR;
    #pragma unroll
    for (int o = 1; o < 32; o <<= 1) {
        int t = __shfl_down_sync(0xffffffffu, b, o);
        if (lane < 32 - o) b = min(b, t);
    }
    int carryR = __shfl_down_sync(0xffffffffu, b, 1);
    if (lane == 31) carryR = SENT;

    const int totL = __shfl_sync(0xffffffffu, a, 31);
    const int totR = __shfl_sync(0xffffffffu, b, 0);
    if (lane == 0) {
        sL[rlocal][quarter] = totL;
        sR[rlocal][quarter] = totR;
    }
    __syncthreads();
    #pragma unroll
    for (int q = 0; q < 4; q++) {
        if (q < quarter) carryL = max(carryL, sL[rlocal][q]);
        if (q > quarter) carryR = min(carryR, sR[rlocal][q]);
    }

    float res[8];
    #pragma unroll
    for (int p = 0; p < 8; p++) {
        const int idx = base + p;
        const unsigned ml = mask & (0xFFu >> (7 - p));
        const unsigned mr = mask & (0xFFu << p);
        const int zl = ml ? (base + 31 - __clz(ml)) : carryL;
        const int zr = mr ? (base + __ffs(mr) - 1) : carryR;
        const int d = min(idx - zl, zr - idx);
        const float df = (float)d;
        res[p] = (d >= (1 << 29)) ? BIGF : df * df;
    }

    float4* __restrict__ o4 = (float4*)(g_f2 + prow * W) + base / 4;
    o4[0] = make_float4(res[0], res[1], res[2], res[3]);
    o4[1] = make_float4(res[4], res[5], res[6], res[7]);

    // PDL: signal dependent kernel may begin its prologue.
    cudaTriggerProgrammaticLaunchCompletion();
}

// ---------------------------------------------------------------------------
// Pass 2: out[i,j] = sqrt( min_k f2[k,j] + (i-k)^2 ).
// Fast path: +-3 window (10 branchless loads, 7 taps). If m <= 9 it's the
// global min ((i-k)^2 >= 16 outside). P(fail) ~ 2^-19/pixel: needs ALL 7
// window rows jointly bad. Slow path: +-8 window; if m still > 64, exact
// full-column fallback. Exact on any input.
// ---------------------------------------------------------------------------
__global__ void __launch_bounds__(256, 8) col_parabola_kernel(float* __restrict__ out) {
    const int j = blockIdx.x * 256 + threadIdx.x;  // column
    const int ib = blockIdx.y * 4;                 // first output row (== padded base)

    // PDL: wait until producer kernel's results are visible.
    cudaGridDependencySynchronize();

    // Fast window: padded rows ib+5 .. ib+14 cover +-3 of output rows ib..ib+3.
    float win[10];
    #pragma unroll
    for (int k = 0; k < 10; k++) win[k] = g_f2[(ib + 5 + k) * W + j];

    // Output u centers at win index u+3.
    float m[4];
    #pragma unroll
    for (int u = 0; u < 4; u++) m[u] = win[u + 3];
    #pragma unroll
    for (int d = 1; d <= 3; d++) {
        const float dd = (float)(d * d);
        #pragma unroll
        for (int u = 0; u < 4; u++) {
            m[u] = fminf(m[u], win[u + 3 - d] + dd);
            m[u] = fminf(m[u], win[u + 3 + d] + dd);
        }
    }

    const float mmax = fmaxf(fmaxf(m[0], m[1]), fmaxf(m[2], m[3]));
    if (mmax > 9.0f) {
        // Slow path (~2^-19 per pixel): full +-8 window.
        float w2[20];
        #pragma unroll
        for (int k = 0; k < 20; k++) w2[k] = g_f2[(ib + k) * W + j];
        #pragma unroll
        for (int u = 0; u < 4; u++) m[u] = w2[u + 8];
        #pragma unroll
        for (int d = 1; d <= 8; d++) {
            const float dd = (float)(d * d);
            #pragma unroll
            for (int u = 0; u < 4; u++) {
                m[u] = fminf(m[u], w2[u + 8 - d] + dd);
                m[u] = fminf(m[u], w2[u + 8 + d] + dd);
            }
        }
        #pragma unroll
        for (int u = 0; u < 4; u++) {
            if (m[u] > 64.0f) {
                // Exact full-column fallback (astronomically rare).
                float mv = 3.4e38f;
                for (int k = 0; k < H; k++) {
                    const float di = (float)(ib + u - k);
                    mv = fminf(mv, g_f2[(k + PAD) * W + j] + di * di);
                }
                m[u] = mv;
            }
        }
    }

    #pragma unroll
    for (int u = 0; u < 4; u++) {
        out[(ib + u) * W + j] = sqrt_approx(m[u]);
    }
}

// ---------------------------------------------------------------------------
extern "C" void kernel_launch(void* const* d_in, const int* in_sizes, int n_in,
                              void* d_out, int out_size) {
    const float* img = (const float*)d_in[0];
    float* out = (float*)d_out;

    row_dist_kernel<<<260, 512>>>(img);   // 260 blocks x 4 padded rows = 1040

    // Dependent launch with programmatic serialization (PDL) so the col
    // kernel's launch + prologue overlap the row kernel's tail.
    cudaLaunchConfig_t cfg = {};
    cfg.gridDim = dim3(W / 256, H / 4);
    cfg.blockDim = dim3(256, 1, 1);
    cfg.dynamicSmemBytes = 0;
    cfg.stream = 0;
    cudaLaunchAttribute attrs[1];
    attrs[0].id = cudaLaunchAttributeProgrammaticStreamSerialization;
    attrs[0].val.programmaticStreamSerializationAllowed = 1;
    cfg.attrs = attrs;
    cfg.numAttrs = 1;
    cudaLaunchKernelEx(&cfg, col_parabola_kernel, out);
}